// round 15
// baseline (speedup 1.0000x reference)
#include <cuda_runtime.h>

typedef unsigned long long u64;

// ---------------- problem constants ----------------
constexpr int B_   = 8;
constexpr int N0_  = 50000;
constexpr int N1_  = 12500;
constexpr int E_   = 400000;
constexpr int FIN_ = 3;
constexpr int C_   = 32;
constexpr int K_   = 6;
constexpr int Z_   = 128;
constexpr int DOWN_NNZ_ = N1_ * 4;
constexpr int UP_NNZ_   = N0_ * 3;
constexpr int EPAD_ = E_ + 4 * N0_;                   // padded-CSR capacity
constexpr int XT_N_ = N0_ * 24;                       // transposed-x elements

// ---------------- device scratch (static, no runtime alloc) ----------------
// T planes VERTEX-MAJOR: plane[v*64 + f4] where the 64 float4 = [b*8 + c4].
__device__ float4 g_buf[7][(size_t)N0_ * 64];         // Cheb ring + relu plane
__device__ float  g_xT[XT_N_ + 32];                   // x transposed: [n][b*3+c]
__device__ float  g_S[5][XT_N_ + 32];                 // encoder T1..T5, vertex-major
__device__ float  g_h[(size_t)B_ * N0_ * C_];         // encoder conv output (batch-major)
__device__ float  g_hc[(size_t)B_ * N1_ * C_];        // down-pooled
__device__ float  g_hc2[(size_t)B_ * N1_ * C_];       // decoder linear output
__device__ float  g_z[B_ * Z_];                       // latent
__device__ int    g_rowptr[N0_ + 1];                  // PADDED rowptr (rows multiple of 4)
__device__ int    g_cnt[N0_];                         // zeroed each call
__device__ int    g_cur[N0_ + 1];                     // fill cursor
__device__ int2   g_edges[EPAD_];                     // (src, norm bits); pads = (0, 0.0f)

// ---------------- f32x2 helpers ----------------
__device__ __forceinline__ u64 pack2(float x, float y) {
    u64 r; asm("mov.b64 %0,{%1,%2};" : "=l"(r) : "f"(x), "f"(y)); return r;
}
__device__ __forceinline__ void fma2(u64& acc, u64 a, u64 b) {
    asm("fma.rn.f32x2 %0,%1,%2,%0;" : "+l"(acc) : "l"(a), "l"(b));
}
__device__ __forceinline__ float2 unpack2(u64 v) {
    float2 f; asm("mov.b64 {%0,%1},%2;" : "=f"(f.x), "=f"(f.y) : "l"(v)); return f;
}

// ---------------- CSR prep ----------------
__global__ void k_prep(const int* __restrict__ dst, const float* __restrict__ x,
                       const float* __restrict__ encb) {
    int i = blockIdx.x * blockDim.x + threadIdx.x;
    if (i < E_) atomicAdd(&g_cnt[dst[i]], 1);
    if (i < XT_N_) {
        int w = i / 24, r = i - w * 24;
        int b = r / 3, c = r - 3 * b;
        g_xT[i] = x[((size_t)b * N0_ + w) * 3 + c];
    }
    if (i < B_ * Z_) g_z[i] = encb[i & (Z_ - 1)];
}

__global__ void k_scan() {   // scans PADDED degrees: (deg+3)&~3
    __shared__ int wsum[32];
    __shared__ int carry;
    int t = threadIdx.x;  // 1024 threads
    if (t == 0) carry = 0;
    __syncthreads();
    for (int base = 0; base < N0_; base += 1024) {
        int i = base + t;
        int v = (i < N0_) ? g_cnt[i] : 0;
        int x = (v + 3) & ~3;
#pragma unroll
        for (int d = 1; d < 32; d <<= 1) {
            int y = __shfl_up_sync(0xffffffffu, x, d);
            if ((t & 31) >= d) x += y;
        }
        if ((t & 31) == 31) wsum[t >> 5] = x;
        __syncthreads();
        if (t < 32) {
            int w = wsum[t];
#pragma unroll
            for (int d = 1; d < 32; d <<= 1) {
                int y = __shfl_up_sync(0xffffffffu, w, d);
                if (t >= d) w += y;
            }
            wsum[t] = w;
        }
        __syncthreads();
        int add  = (t >= 32) ? wsum[(t >> 5) - 1] : 0;
        int incl = x + add + carry;
        if (i < N0_) { g_rowptr[i + 1] = incl; g_cur[i + 1] = incl; }
        __syncthreads();
        if (t == 1023) carry = incl;
        __syncthreads();
    }
    if (t == 0) { g_rowptr[0] = 0; g_cur[0] = 0; }
}

__global__ void k_fill(const int* __restrict__ src, const int* __restrict__ dst,
                       const float* __restrict__ norm) {
    int e = blockIdx.x * blockDim.x + threadIdx.x;
    if (e < E_) {
        int d = dst[e];
        int pos = atomicAdd(&g_cur[d], 1);
        g_edges[pos] = make_int2(src[e], __float_as_int(norm[e]));
    }
}

__global__ void k_pad() {
    int i = blockIdx.x * blockDim.x + threadIdx.x;
    if (i >= N0_) return;
    int e = g_cur[i], end = g_rowptr[i + 1];
    for (; e < end; e++) g_edges[e] = make_int2(0, 0);
    g_cnt[i] = 0;
}

// ---------------- encoder propagate (vertex-major; 8-edge unroll) ----------
__global__ void __launch_bounds__(256) enc_prop(int prev_idx, int pp_idx, int next_idx) {
    int w = (blockIdx.x * blockDim.x + threadIdx.x) >> 5;
    if (w >= N0_) return;
    int lane = threadIdx.x & 31;
    bool act = lane < 24;
    const float* prev = (prev_idx < 0) ? g_xT : g_S[prev_idx];
    int lx = act ? lane : 0;

    int beg = g_rowptr[w], end = g_rowptr[w + 1];
    float s = 0.f;
    int p = beg;
    for (; p + 8 <= end; p += 8) {
        int2 e0 = g_edges[p];
        int2 e1 = g_edges[p + 1];
        int2 e2 = g_edges[p + 2];
        int2 e3 = g_edges[p + 3];
        int2 e4 = g_edges[p + 4];
        int2 e5 = g_edges[p + 5];
        int2 e6 = g_edges[p + 6];
        int2 e7 = g_edges[p + 7];
        float v0 = __ldg(prev + (size_t)e0.x * 24 + lx);
        float v1 = __ldg(prev + (size_t)e1.x * 24 + lx);
        float v2 = __ldg(prev + (size_t)e2.x * 24 + lx);
        float v3 = __ldg(prev + (size_t)e3.x * 24 + lx);
        float v4 = __ldg(prev + (size_t)e4.x * 24 + lx);
        float v5 = __ldg(prev + (size_t)e5.x * 24 + lx);
        float v6 = __ldg(prev + (size_t)e6.x * 24 + lx);
        float v7 = __ldg(prev + (size_t)e7.x * 24 + lx);
        s = fmaf(__int_as_float(e0.y), v0, s);
        s = fmaf(__int_as_float(e1.y), v1, s);
        s = fmaf(__int_as_float(e2.y), v2, s);
        s = fmaf(__int_as_float(e3.y), v3, s);
        s = fmaf(__int_as_float(e4.y), v4, s);
        s = fmaf(__int_as_float(e5.y), v5, s);
        s = fmaf(__int_as_float(e6.y), v6, s);
        s = fmaf(__int_as_float(e7.y), v7, s);
    }
    for (; p < end; p += 4) {
        int2 e0 = g_edges[p];
        int2 e1 = g_edges[p + 1];
        int2 e2 = g_edges[p + 2];
        int2 e3 = g_edges[p + 3];
        float v0 = __ldg(prev + (size_t)e0.x * 24 + lx);
        float v1 = __ldg(prev + (size_t)e1.x * 24 + lx);
        float v2 = __ldg(prev + (size_t)e2.x * 24 + lx);
        float v3 = __ldg(prev + (size_t)e3.x * 24 + lx);
        s = fmaf(__int_as_float(e0.y), v0, s);
        s = fmaf(__int_as_float(e1.y), v1, s);
        s = fmaf(__int_as_float(e2.y), v2, s);
        s = fmaf(__int_as_float(e3.y), v3, s);
    }
    if (act) {
        int idx = w * 24 + lane;
        float tk = (pp_idx == -2) ? s
                 : 2.f * s - ((pp_idx < 0) ? g_xT[idx] : g_S[pp_idx][idx]);
        g_S[next_idx][idx] = tk;
    }
}

// ---------------- encoder combine ----------------
__global__ void enc_combine(const float* __restrict__ Wenc, const float* __restrict__ benc) {
    __shared__ float Wsm[K_ * FIN_ * C_];
    __shared__ float bsm[C_];
    int t = threadIdx.x;
    for (int i = t; i < K_ * FIN_ * C_; i += blockDim.x) Wsm[i] = Wenc[i];
    if (t < C_) bsm[t] = benc[t];
    __syncthreads();
    int w = (blockIdx.x * blockDim.x + t) >> 5;
    if (w >= N0_) return;
    int lane = t & 31;
    bool act = lane < 24;
    float tv[6];
    tv[0] = act ? g_xT[w * 24 + lane] : 0.f;
#pragma unroll
    for (int k = 1; k < 6; k++) tv[k] = act ? g_S[k - 1][w * 24 + lane] : 0.f;
#pragma unroll
    for (int b = 0; b < B_; b++) {
        float a = bsm[lane];
#pragma unroll
        for (int k = 0; k < 6; k++)
#pragma unroll
            for (int c = 0; c < 3; c++) {
                float v = __shfl_sync(0xffffffffu, tv[k], b * 3 + c);
                a = fmaf(v, Wsm[(k * 3 + c) * C_ + lane], a);
            }
        g_h[(b * N0_ + w) * C_ + lane] = fmaxf(a, 0.f);
    }
}

// ---------------- pools ----------------
__global__ void down_pool(const int* __restrict__ dcol, const float* __restrict__ dval) {
    int wi = (blockIdx.x * blockDim.x + threadIdx.x) >> 5;
    if (wi >= B_ * N1_) return;
    int lane = threadIdx.x & 31;
    int b = wi / N1_, r = wi - b * N1_;
    float a = 0.f;
#pragma unroll
    for (int j = 0; j < 4; j++) {
        int   col = dcol[4 * r + j];
        float v   = dval[4 * r + j];
        a += v * g_h[(b * N0_ + col) * C_ + lane];
    }
    g_hc[(b * N1_ + r) * C_ + lane] = a;
}

__global__ void up_pool(const int* __restrict__ ucol, const float* __restrict__ uval) {
    int wi = (blockIdx.x * blockDim.x + threadIdx.x) >> 5;
    if (wi >= B_ * N0_) return;
    int lane = threadIdx.x & 31;
    int b = wi / N0_, i = wi - b * N0_;
    float a = 0.f;
#pragma unroll
    for (int j = 0; j < 3; j++) {
        int   col = ucol[3 * i + j];
        float v   = uval[3 * i + j];
        a += v * g_hc2[(b * N1_ + col) * C_ + lane];
    }
    float* P0 = (float*)g_buf[0];
    P0[(size_t)i * 256 + b * 32 + lane] = a;
}

// ---------------- dense linears ----------------
__global__ void __launch_bounds__(256) enc_lin(const float* __restrict__ We) {
    constexpr int SLAB = 512;
    __shared__ float hs[B_][SLAB];
    int base = blockIdx.x * SLAB;
    int t = threadIdx.x;
    int z = t & 127, bb = (t >> 7) * 4;
    for (int idx = t; idx < B_ * SLAB; idx += 256) {
        int b = idx >> 9, kk = idx & (SLAB - 1);
        int g = base + kk;
        hs[b][kk] = (g < N1_ * C_) ? g_hc[(size_t)b * (N1_ * C_) + g] : 0.f;
    }
    __syncthreads();
    int lim = min(SLAB, N1_ * C_ - base);
    float a0 = 0.f, a1 = 0.f, a2 = 0.f, a3 = 0.f;
#pragma unroll 8
    for (int kk = 0; kk < lim; kk++) {
        float w = __ldcs(We + (size_t)(base + kk) * Z_ + z);
        a0 = fmaf(hs[bb + 0][kk], w, a0);
        a1 = fmaf(hs[bb + 1][kk], w, a1);
        a2 = fmaf(hs[bb + 2][kk], w, a2);
        a3 = fmaf(hs[bb + 3][kk], w, a3);
    }
    atomicAdd(&g_z[(bb + 0) * Z_ + z], a0);
    atomicAdd(&g_z[(bb + 1) * Z_ + z], a1);
    atomicAdd(&g_z[(bb + 2) * Z_ + z], a2);
    atomicAdd(&g_z[(bb + 3) * Z_ + z], a3);
}

__global__ void __launch_bounds__(256) dec_lin(const float* __restrict__ Wd,
                                               const float* __restrict__ bd) {
    __shared__ float zsm[B_ * Z_];
    int t = threadIdx.x;
    for (int i = t; i < B_ * Z_; i += 256) zsm[i] = g_z[i];
    __syncthreads();
    constexpr int J4 = N1_ * C_ / 4;
    int j4 = blockIdx.x * 256 + t;
    if (j4 >= J4) return;
    const float4* W4 = (const float4*)Wd;
    float4 bias = __ldg(((const float4*)bd) + j4);
    float4 a[B_];
#pragma unroll
    for (int b = 0; b < B_; b++) a[b] = bias;
#pragma unroll 4
    for (int zk = 0; zk < Z_; zk++) {
        float4 w = __ldcs(W4 + (size_t)zk * J4 + j4);
#pragma unroll
        for (int b = 0; b < B_; b++) {
            float zv = zsm[b * Z_ + zk];
            a[b].x = fmaf(zv, w.x, a[b].x);
            a[b].y = fmaf(zv, w.y, a[b].y);
            a[b].z = fmaf(zv, w.z, a[b].z);
            a[b].w = fmaf(zv, w.w, a[b].w);
        }
    }
    float4* out4 = (float4*)g_hc2;
#pragma unroll
    for (int b = 0; b < B_; b++) {
        float4 r = a[b];
        r.x = fmaxf(r.x, 0.f); r.y = fmaxf(r.y, 0.f);
        r.z = fmaxf(r.z, 0.f); r.w = fmaxf(r.w, 0.f);
        out4[(size_t)b * J4 + j4] = r;
    }
}

// ---------------- cheb step, y=2 split: warp covers 32 float4s (4 batches) ----------------
// 1 x LDG.128 per edge per warp; 4-edge unroll -> 4 loads in flight; 100k warps.
template <bool K1>
__global__ void __launch_bounds__(256) cheb_step(int prev_idx, int pp_idx, int next_idx) {
    int w = (blockIdx.x * blockDim.x + threadIdx.x) >> 5;
    if (w >= N0_) return;
    int lane = threadIdx.x & 31;
    int off = blockIdx.y << 5;                     // 0 or 32
    int fl = off + lane;

    const float4* Tp = g_buf[prev_idx];
    int beg = g_rowptr[w], end = g_rowptr[w + 1];
    float4 s = make_float4(0.f, 0.f, 0.f, 0.f);
    for (int p = beg; p < end; p += 4) {           // rows padded to 4: no remainder
        int2 e0 = g_edges[p];
        int2 e1 = g_edges[p + 1];
        int2 e2 = g_edges[p + 2];
        int2 e3 = g_edges[p + 3];
        float4 a0 = Tp[(size_t)e0.x * 64 + fl];
        float4 a1 = Tp[(size_t)e1.x * 64 + fl];
        float4 a2 = Tp[(size_t)e2.x * 64 + fl];
        float4 a3 = Tp[(size_t)e3.x * 64 + fl];
        float n0 = __int_as_float(e0.y), n1 = __int_as_float(e1.y);
        float n2 = __int_as_float(e2.y), n3 = __int_as_float(e3.y);
        s.x = fmaf(n0, a0.x, s.x); s.y = fmaf(n0, a0.y, s.y);
        s.z = fmaf(n0, a0.z, s.z); s.w = fmaf(n0, a0.w, s.w);
        s.x = fmaf(n1, a1.x, s.x); s.y = fmaf(n1, a1.y, s.y);
        s.z = fmaf(n1, a1.z, s.z); s.w = fmaf(n1, a1.w, s.w);
        s.x = fmaf(n2, a2.x, s.x); s.y = fmaf(n2, a2.y, s.y);
        s.z = fmaf(n2, a2.z, s.z); s.w = fmaf(n2, a2.w, s.w);
        s.x = fmaf(n3, a3.x, s.x); s.y = fmaf(n3, a3.y, s.y);
        s.z = fmaf(n3, a3.z, s.z); s.w = fmaf(n3, a3.w, s.w);
    }

    size_t base = (size_t)w * 64 + fl;
    float4 tk;
    if (K1) {
        tk = s;
    } else {
        float4 pp = g_buf[pp_idx][base];
        tk = make_float4(2.f * s.x - pp.x, 2.f * s.y - pp.y,
                         2.f * s.z - pp.z, 2.f * s.w - pp.w);
    }
    g_buf[next_idx][base] = tk;
}

// ---------------- fused final step + combine32 (conv0) ----------------
// Computes T5 in-register (gather from prev, recursion with pp), then
// out = relu(bias + sum_{k=0..4} P[idx_k] @ W_k + T5 @ W_5) -> relu plane.
__global__ void __launch_bounds__(256) fused_step_combine32(
    int prev_idx, int pp_idx,
    int i0, int i1, int i2, int i3, int i4,
    const float* __restrict__ W, const float* __restrict__ bias, int relu_out_idx) {
    __shared__ __align__(16) float tkbuf[8][256];
    int w = (blockIdx.x * blockDim.x + threadIdx.x) >> 5;
    if (w >= N0_) return;
    int lane = threadIdx.x & 31;
    int warp = threadIdx.x >> 5;

    // gather (full vertex, 2-edge unroll, 2 x LDG.128 per edge)
    const float4* Tp = g_buf[prev_idx];
    int beg = g_rowptr[w], end = g_rowptr[w + 1];
    float4 sA = make_float4(0.f, 0.f, 0.f, 0.f);
    float4 sB = make_float4(0.f, 0.f, 0.f, 0.f);
    for (int p = beg; p < end; p += 2) {
        int2 e0 = g_edges[p];
        int2 e1 = g_edges[p + 1];
        const float4* q0 = Tp + (size_t)e0.x * 64;
        const float4* q1 = Tp + (size_t)e1.x * 64;
        float4 a0 = q0[lane], b0 = q0[lane + 32];
        float4 a1 = q1[lane], b1 = q1[lane + 32];
        float n0 = __int_as_float(e0.y), n1 = __int_as_float(e1.y);
        sA.x = fmaf(n0, a0.x, sA.x); sA.y = fmaf(n0, a0.y, sA.y);
        sA.z = fmaf(n0, a0.z, sA.z); sA.w = fmaf(n0, a0.w, sA.w);
        sB.x = fmaf(n0, b0.x, sB.x); sB.y = fmaf(n0, b0.y, sB.y);
        sB.z = fmaf(n0, b0.z, sB.z); sB.w = fmaf(n0, b0.w, sB.w);
        sA.x = fmaf(n1, a1.x, sA.x); sA.y = fmaf(n1, a1.y, sA.y);
        sA.z = fmaf(n1, a1.z, sA.z); sA.w = fmaf(n1, a1.w, sA.w);
        sB.x = fmaf(n1, b1.x, sB.x); sB.y = fmaf(n1, b1.y, sB.y);
        sB.z = fmaf(n1, b1.z, sB.z); sB.w = fmaf(n1, b1.w, sB.w);
    }
    size_t vb = (size_t)w * 64;
    float4 pA = g_buf[pp_idx][vb + lane];
    float4 pB = g_buf[pp_idx][vb + 32 + lane];
    float4 t5A = make_float4(2.f * sA.x - pA.x, 2.f * sA.y - pA.y,
                             2.f * sA.z - pA.z, 2.f * sA.w - pA.w);
    float4 t5B = make_float4(2.f * sB.x - pB.x, 2.f * sB.y - pB.y,
                             2.f * sB.z - pB.z, 2.f * sB.w - pB.w);

    // combine
    float acc[B_];
    float binit = bias[lane];
#pragma unroll
    for (int b = 0; b < B_; b++) acc[b] = binit;

    int idxs[5] = {i0, i1, i2, i3, i4};
    float4* tb4 = (float4*)&tkbuf[warp][0];
#pragma unroll
    for (int k = 0; k < 6; k++) {
        if (k < 5) {
            const float4* T4 = g_buf[idxs[k]];
            tb4[lane]      = T4[vb + lane];
            tb4[lane + 32] = T4[vb + 32 + lane];
        } else {
            tb4[lane]      = t5A;
            tb4[lane + 32] = t5B;
        }
        __syncwarp();
        const float* Wk = W + k * C_ * C_;
        u64 w2p[16];
#pragma unroll
        for (int i = 0; i < 16; i++)
            w2p[i] = pack2(Wk[(2 * i) * C_ + lane], Wk[(2 * i + 1) * C_ + lane]);
#pragma unroll
        for (int b = 0; b < B_; b++) {
            const u64* tb = (const u64*)&tkbuf[warp][b * 32];
            u64 a2 = 0;
#pragma unroll
            for (int i = 0; i < 16; i++) fma2(a2, tb[i], w2p[i]);
            float2 cc = unpack2(a2);
            acc[b] += cc.x + cc.y;
        }
        __syncwarp();
    }

    float* outp = (float*)g_buf[relu_out_idx];
#pragma unroll
    for (int b = 0; b < B_; b++)
        outp[vb * 4 + b * 32 + lane] = fmaxf(acc[b], 0.f);
}

// ---------------- fused final step + combine3 (conv1, no bias) ----------------
__global__ void __launch_bounds__(256) fused_step_combine3(
    int prev_idx, int pp_idx,
    int i0, int i1, int i2, int i3, int i4,
    const float* __restrict__ W, float* __restrict__ out3) {
    __shared__ __align__(16) float tkbuf[8][256];
    int gt = blockIdx.x * blockDim.x + threadIdx.x;
    if (gt < N0_) g_cnt[gt] = 0;                   // fold next-call reset into last kernel
    int w = gt >> 5;
    if (w >= N0_) return;
    int lane = threadIdx.x & 31;
    int warp = threadIdx.x >> 5;

    // gather
    const float4* Tp = g_buf[prev_idx];
    int beg = g_rowptr[w], end = g_rowptr[w + 1];
    float4 sA = make_float4(0.f, 0.f, 0.f, 0.f);
    float4 sB = make_float4(0.f, 0.f, 0.f, 0.f);
    for (int p = beg; p < end; p += 2) {
        int2 e0 = g_edges[p];
        int2 e1 = g_edges[p + 1];
        const float4* q0 = Tp + (size_t)e0.x * 64;
        const float4* q1 = Tp + (size_t)e1.x * 64;
        float4 a0 = q0[lane], b0 = q0[lane + 32];
        float4 a1 = q1[lane], b1 = q1[lane + 32];
        float n0 = __int_as_float(e0.y), n1 = __int_as_float(e1.y);
        sA.x = fmaf(n0, a0.x, sA.x); sA.y = fmaf(n0, a0.y, sA.y);
        sA.z = fmaf(n0, a0.z, sA.z); sA.w = fmaf(n0, a0.w, sA.w);
        sB.x = fmaf(n0, b0.x, sB.x); sB.y = fmaf(n0, b0.y, sB.y);
        sB.z = fmaf(n0, b0.z, sB.z); sB.w = fmaf(n0, b0.w, sB.w);
        sA.x = fmaf(n1, a1.x, sA.x); sA.y = fmaf(n1, a1.y, sA.y);
        sA.z = fmaf(n1, a1.z, sA.z); sA.w = fmaf(n1, a1.w, sA.w);
        sB.x = fmaf(n1, b1.x, sB.x); sB.y = fmaf(n1, b1.y, sB.y);
        sB.z = fmaf(n1, b1.z, sB.z); sB.w = fmaf(n1, b1.w, sB.w);
    }
    size_t vb = (size_t)w * 64;
    float4 pA = g_buf[pp_idx][vb + lane];
    float4 pB = g_buf[pp_idx][vb + 32 + lane];
    float4 t5A = make_float4(2.f * sA.x - pA.x, 2.f * sA.y - pA.y,
                             2.f * sA.z - pA.z, 2.f * sA.w - pA.w);
    float4 t5B = make_float4(2.f * sB.x - pB.x, 2.f * sB.y - pB.y,
                             2.f * sB.z - pB.z, 2.f * sB.w - pB.w);

    bool act = lane < 24;
    int b = act ? lane / 3 : 0;
    int c = act ? lane - 3 * (lane / 3) : 0;

    float acc = 0.f;
    int idxs[5] = {i0, i1, i2, i3, i4};
    float4* tb4 = (float4*)&tkbuf[warp][0];
#pragma unroll
    for (int k = 0; k < 6; k++) {
        if (k < 5) {
            const float4* T4 = g_buf[idxs[k]];
            tb4[lane]      = T4[vb + lane];
            tb4[lane + 32] = T4[vb + 32 + lane];
        } else {
            tb4[lane]      = t5A;
            tb4[lane + 32] = t5B;
        }
        __syncwarp();
        const float* Wk = W + k * C_ * FIN_;       // [32][3]
        const u64* tb = (const u64*)&tkbuf[warp][b * 32];
        u64 a2 = 0;
#pragma unroll
        for (int i = 0; i < 16; i++) {
            u64 wp = pack2(Wk[(2 * i) * FIN_ + c], Wk[(2 * i + 1) * FIN_ + c]);
            fma2(a2, tb[i], wp);
        }
        float2 cc = unpack2(a2);
        acc += cc.x + cc.y;
        __syncwarp();
    }

    if (act)
        out3[((size_t)b * N0_ + w) * FIN_ + c] = acc;
}

// ---------------- launch ----------------
extern "C" void kernel_launch(void* const* d_in, const int* in_sizes, int n_in,
                              void* d_out, int out_size) {
    (void)in_sizes; (void)n_in; (void)out_size;
    const float* x      = (const float*)d_in[0];
    const int*   eidx   = (const int*)  d_in[1];
    const float* Anorm  = (const float*)d_in[2];
    const int*   didx   = (const int*)  d_in[3];
    const float* dval   = (const float*)d_in[4];
    const int*   uidx   = (const int*)  d_in[5];
    const float* uval   = (const float*)d_in[6];
    const float* Wenc0  = (const float*)d_in[7];
    const float* benc0  = (const float*)d_in[8];
    const float* Wdec0  = (const float*)d_in[9];
    const float* bdec0  = (const float*)d_in[10];
    const float* Wdec1  = (const float*)d_in[11];
    const float* encW   = (const float*)d_in[12];
    const float* encb   = (const float*)d_in[13];
    const float* decW   = (const float*)d_in[14];
    const float* decb   = (const float*)d_in[15];
    float* out = (float*)d_out;

    const int GPV  = N0_ * 32 / 256;          // 6250 warp-per-vertex
    const dim3 GPV2(GPV, 2);                  // half-vertex split
    const int GE   = (E_ + 255) / 256;
    const int GN0  = (N0_ + 255) / 256;
    const int GPREP = (XT_N_ + 255) / 256;

    // CSR prep
    k_prep<<<GPREP, 256>>>(eidx + E_, x, encb);
    k_scan<<<1, 1024>>>();
    k_fill<<<GE, 256>>>(eidx, eidx + E_, Anorm);
    k_pad<<<GN0, 256>>>();

    // ---- encoder conv ----
    enc_prop<<<GPV, 256>>>(-1, -2, 0);   // T1
    enc_prop<<<GPV, 256>>>( 0, -1, 1);   // T2
    enc_prop<<<GPV, 256>>>( 1,  0, 2);   // T3
    enc_prop<<<GPV, 256>>>( 2,  1, 3);   // T4
    enc_prop<<<GPV, 256>>>( 3,  2, 4);   // T5
    enc_combine<<<GPV, 256>>>(Wenc0, benc0);

    // ---- down pool ----
    down_pool<<<B_ * N1_ * 32 / 256, 256>>>(didx + DOWN_NNZ_, dval);

    // ---- encoder linear ----
    enc_lin<<<(N1_ * C_ + 511) / 512, 256>>>(encW);

    // ---- decoder linear (+relu) ----
    dec_lin<<<(N1_ * C_ / 4 + 255) / 256, 256>>>(decW, decb);

    // ---- up pool -> g_buf[0] vertex-major ----
    up_pool<<<B_ * N0_ * 32 / 256, 256>>>(uidx + UP_NNZ_, uval);

    // ---- decoder conv0: T1..T4 -> g_buf[1..4]; fused T5+combine -> relu -> g_buf[6] ----
    cheb_step<true ><<<GPV2, 256>>>(0, 0, 1);
    cheb_step<false><<<GPV2, 256>>>(1, 0, 2);
    cheb_step<false><<<GPV2, 256>>>(2, 1, 3);
    cheb_step<false><<<GPV2, 256>>>(3, 2, 4);
    fused_step_combine32<<<GPV, 256>>>(4, 3, 0, 1, 2, 3, 4, Wdec0, bdec0, 6);

    // ---- decoder conv1: T0 = g_buf[6]; T1..T4 -> g_buf[0..3]; fused T5+combine -> d_out ----
    cheb_step<true ><<<GPV2, 256>>>(6, 0, 0);
    cheb_step<false><<<GPV2, 256>>>(0, 6, 1);
    cheb_step<false><<<GPV2, 256>>>(1, 0, 2);
    cheb_step<false><<<GPV2, 256>>>(2, 1, 3);
    fused_step_combine3<<<GPV, 256>>>(3, 2, 6, 0, 1, 2, 3, Wdec1, out);
}

// round 16
// speedup vs baseline: 1.1237x; 1.1237x over previous
#include <cuda_runtime.h>

typedef unsigned long long u64;

// ---------------- problem constants ----------------
constexpr int B_   = 8;
constexpr int N0_  = 50000;
constexpr int N1_  = 12500;
constexpr int E_   = 400000;
constexpr int FIN_ = 3;
constexpr int C_   = 32;
constexpr int K_   = 6;
constexpr int Z_   = 128;
constexpr int DOWN_NNZ_ = N1_ * 4;
constexpr int UP_NNZ_   = N0_ * 3;
constexpr int EPAD_ = E_ + 4 * N0_;                   // padded-CSR capacity
constexpr int XT_N_ = N0_ * 24;                       // transposed-x elements

// ---------------- device scratch (static, no runtime alloc) ----------------
// T planes VERTEX-MAJOR: plane[v*64 + f4] where the 64 float4 = [b*8 + c4].
__device__ float4 g_buf[7][(size_t)N0_ * 64];         // Cheb ring + relu plane
__device__ float  g_xT[XT_N_ + 32];                   // x transposed: [n][b*3+c]
__device__ float  g_S[5][XT_N_ + 32];                 // encoder T1..T5, vertex-major
__device__ float  g_h[(size_t)B_ * N0_ * C_];         // encoder conv output (batch-major)
__device__ float  g_hc[(size_t)B_ * N1_ * C_];        // down-pooled
__device__ float  g_hc2[(size_t)B_ * N1_ * C_];       // decoder linear output
__device__ float  g_z[B_ * Z_];                       // latent
__device__ int    g_rowptr[N0_ + 1];                  // PADDED rowptr (rows multiple of 4)
__device__ int    g_cnt[N0_];                         // zeroed each call
__device__ int    g_cur[N0_ + 1];                     // fill cursor
__device__ int2   g_edges[EPAD_];                     // (src, norm bits); pads = (0, 0.0f)

// ---------------- f32x2 helpers ----------------
__device__ __forceinline__ u64 pack2(float x, float y) {
    u64 r; asm("mov.b64 %0,{%1,%2};" : "=l"(r) : "f"(x), "f"(y)); return r;
}
__device__ __forceinline__ void fma2(u64& acc, u64 a, u64 b) {
    asm("fma.rn.f32x2 %0,%1,%2,%0;" : "+l"(acc) : "l"(a), "l"(b));
}
__device__ __forceinline__ float2 unpack2(u64 v) {
    float2 f; asm("mov.b64 {%0,%1},%2;" : "=f"(f.x), "=f"(f.y) : "l"(v)); return f;
}

// ---------------- CSR prep ----------------
__global__ void k_prep(const int* __restrict__ dst, const float* __restrict__ x,
                       const float* __restrict__ encb) {
    int i = blockIdx.x * blockDim.x + threadIdx.x;
    if (i < E_) atomicAdd(&g_cnt[dst[i]], 1);
    if (i < XT_N_) {
        int w = i / 24, r = i - w * 24;
        int b = r / 3, c = r - 3 * b;
        g_xT[i] = x[((size_t)b * N0_ + w) * 3 + c];
    }
    if (i < B_ * Z_) g_z[i] = encb[i & (Z_ - 1)];
}

__global__ void k_scan() {   // scans PADDED degrees: (deg+3)&~3
    __shared__ int wsum[32];
    __shared__ int carry;
    int t = threadIdx.x;  // 1024 threads
    if (t == 0) carry = 0;
    __syncthreads();
    for (int base = 0; base < N0_; base += 1024) {
        int i = base + t;
        int v = (i < N0_) ? g_cnt[i] : 0;
        int x = (v + 3) & ~3;
#pragma unroll
        for (int d = 1; d < 32; d <<= 1) {
            int y = __shfl_up_sync(0xffffffffu, x, d);
            if ((t & 31) >= d) x += y;
        }
        if ((t & 31) == 31) wsum[t >> 5] = x;
        __syncthreads();
        if (t < 32) {
            int w = wsum[t];
#pragma unroll
            for (int d = 1; d < 32; d <<= 1) {
                int y = __shfl_up_sync(0xffffffffu, w, d);
                if (t >= d) w += y;
            }
            wsum[t] = w;
        }
        __syncthreads();
        int add  = (t >= 32) ? wsum[(t >> 5) - 1] : 0;
        int incl = x + add + carry;
        if (i < N0_) { g_rowptr[i + 1] = incl; g_cur[i + 1] = incl; }
        __syncthreads();
        if (t == 1023) carry = incl;
        __syncthreads();
    }
    if (t == 0) { g_rowptr[0] = 0; g_cur[0] = 0; }
}

__global__ void k_fill(const int* __restrict__ src, const int* __restrict__ dst,
                       const float* __restrict__ norm) {
    int e = blockIdx.x * blockDim.x + threadIdx.x;
    if (e < E_) {
        int d = dst[e];
        int pos = atomicAdd(&g_cur[d], 1);
        g_edges[pos] = make_int2(src[e], __float_as_int(norm[e]));
    }
}

__global__ void k_pad() {
    int i = blockIdx.x * blockDim.x + threadIdx.x;
    if (i >= N0_) return;
    int e = g_cur[i], end = g_rowptr[i + 1];
    for (; e < end; e++) g_edges[e] = make_int2(0, 0);
    g_cnt[i] = 0;
}

// ---------------- encoder propagate (vertex-major; 8-edge unroll) ----------
__global__ void __launch_bounds__(256) enc_prop(int prev_idx, int pp_idx, int next_idx) {
    int w = (blockIdx.x * blockDim.x + threadIdx.x) >> 5;
    if (w >= N0_) return;
    int lane = threadIdx.x & 31;
    bool act = lane < 24;
    const float* prev = (prev_idx < 0) ? g_xT : g_S[prev_idx];
    int lx = act ? lane : 0;

    int beg = g_rowptr[w], end = g_rowptr[w + 1];
    float s = 0.f;
    int p = beg;
    for (; p + 8 <= end; p += 8) {
        int2 e0 = g_edges[p];
        int2 e1 = g_edges[p + 1];
        int2 e2 = g_edges[p + 2];
        int2 e3 = g_edges[p + 3];
        int2 e4 = g_edges[p + 4];
        int2 e5 = g_edges[p + 5];
        int2 e6 = g_edges[p + 6];
        int2 e7 = g_edges[p + 7];
        float v0 = __ldg(prev + (size_t)e0.x * 24 + lx);
        float v1 = __ldg(prev + (size_t)e1.x * 24 + lx);
        float v2 = __ldg(prev + (size_t)e2.x * 24 + lx);
        float v3 = __ldg(prev + (size_t)e3.x * 24 + lx);
        float v4 = __ldg(prev + (size_t)e4.x * 24 + lx);
        float v5 = __ldg(prev + (size_t)e5.x * 24 + lx);
        float v6 = __ldg(prev + (size_t)e6.x * 24 + lx);
        float v7 = __ldg(prev + (size_t)e7.x * 24 + lx);
        s = fmaf(__int_as_float(e0.y), v0, s);
        s = fmaf(__int_as_float(e1.y), v1, s);
        s = fmaf(__int_as_float(e2.y), v2, s);
        s = fmaf(__int_as_float(e3.y), v3, s);
        s = fmaf(__int_as_float(e4.y), v4, s);
        s = fmaf(__int_as_float(e5.y), v5, s);
        s = fmaf(__int_as_float(e6.y), v6, s);
        s = fmaf(__int_as_float(e7.y), v7, s);
    }
    for (; p < end; p += 4) {
        int2 e0 = g_edges[p];
        int2 e1 = g_edges[p + 1];
        int2 e2 = g_edges[p + 2];
        int2 e3 = g_edges[p + 3];
        float v0 = __ldg(prev + (size_t)e0.x * 24 + lx);
        float v1 = __ldg(prev + (size_t)e1.x * 24 + lx);
        float v2 = __ldg(prev + (size_t)e2.x * 24 + lx);
        float v3 = __ldg(prev + (size_t)e3.x * 24 + lx);
        s = fmaf(__int_as_float(e0.y), v0, s);
        s = fmaf(__int_as_float(e1.y), v1, s);
        s = fmaf(__int_as_float(e2.y), v2, s);
        s = fmaf(__int_as_float(e3.y), v3, s);
    }
    if (act) {
        int idx = w * 24 + lane;
        float tk = (pp_idx == -2) ? s
                 : 2.f * s - ((pp_idx < 0) ? g_xT[idx] : g_S[pp_idx][idx]);
        g_S[next_idx][idx] = tk;
    }
}

// ---------------- encoder combine ----------------
__global__ void enc_combine(const float* __restrict__ Wenc, const float* __restrict__ benc) {
    __shared__ float Wsm[K_ * FIN_ * C_];
    __shared__ float bsm[C_];
    int t = threadIdx.x;
    for (int i = t; i < K_ * FIN_ * C_; i += blockDim.x) Wsm[i] = Wenc[i];
    if (t < C_) bsm[t] = benc[t];
    __syncthreads();
    int w = (blockIdx.x * blockDim.x + t) >> 5;
    if (w >= N0_) return;
    int lane = t & 31;
    bool act = lane < 24;
    float tv[6];
    tv[0] = act ? g_xT[w * 24 + lane] : 0.f;
#pragma unroll
    for (int k = 1; k < 6; k++) tv[k] = act ? g_S[k - 1][w * 24 + lane] : 0.f;
#pragma unroll
    for (int b = 0; b < B_; b++) {
        float a = bsm[lane];
#pragma unroll
        for (int k = 0; k < 6; k++)
#pragma unroll
            for (int c = 0; c < 3; c++) {
                float v = __shfl_sync(0xffffffffu, tv[k], b * 3 + c);
                a = fmaf(v, Wsm[(k * 3 + c) * C_ + lane], a);
            }
        g_h[(b * N0_ + w) * C_ + lane] = fmaxf(a, 0.f);
    }
}

// ---------------- pools ----------------
__global__ void down_pool(const int* __restrict__ dcol, const float* __restrict__ dval) {
    int wi = (blockIdx.x * blockDim.x + threadIdx.x) >> 5;
    if (wi >= B_ * N1_) return;
    int lane = threadIdx.x & 31;
    int b = wi / N1_, r = wi - b * N1_;
    float a = 0.f;
#pragma unroll
    for (int j = 0; j < 4; j++) {
        int   col = dcol[4 * r + j];
        float v   = dval[4 * r + j];
        a += v * g_h[(b * N0_ + col) * C_ + lane];
    }
    g_hc[(b * N1_ + r) * C_ + lane] = a;
}

__global__ void up_pool(const int* __restrict__ ucol, const float* __restrict__ uval) {
    int wi = (blockIdx.x * blockDim.x + threadIdx.x) >> 5;
    if (wi >= B_ * N0_) return;
    int lane = threadIdx.x & 31;
    int b = wi / N0_, i = wi - b * N0_;
    float a = 0.f;
#pragma unroll
    for (int j = 0; j < 3; j++) {
        int   col = ucol[3 * i + j];
        float v   = uval[3 * i + j];
        a += v * g_hc2[(b * N1_ + col) * C_ + lane];
    }
    float* P0 = (float*)g_buf[0];
    P0[(size_t)i * 256 + b * 32 + lane] = a;
}

// ---------------- dense linears ----------------
__global__ void __launch_bounds__(256) enc_lin(const float* __restrict__ We) {
    constexpr int SLAB = 512;
    __shared__ float hs[B_][SLAB];
    int base = blockIdx.x * SLAB;
    int t = threadIdx.x;
    int z = t & 127, bb = (t >> 7) * 4;
    for (int idx = t; idx < B_ * SLAB; idx += 256) {
        int b = idx >> 9, kk = idx & (SLAB - 1);
        int g = base + kk;
        hs[b][kk] = (g < N1_ * C_) ? g_hc[(size_t)b * (N1_ * C_) + g] : 0.f;
    }
    __syncthreads();
    int lim = min(SLAB, N1_ * C_ - base);
    float a0 = 0.f, a1 = 0.f, a2 = 0.f, a3 = 0.f;
#pragma unroll 8
    for (int kk = 0; kk < lim; kk++) {
        float w = __ldcs(We + (size_t)(base + kk) * Z_ + z);
        a0 = fmaf(hs[bb + 0][kk], w, a0);
        a1 = fmaf(hs[bb + 1][kk], w, a1);
        a2 = fmaf(hs[bb + 2][kk], w, a2);
        a3 = fmaf(hs[bb + 3][kk], w, a3);
    }
    atomicAdd(&g_z[(bb + 0) * Z_ + z], a0);
    atomicAdd(&g_z[(bb + 1) * Z_ + z], a1);
    atomicAdd(&g_z[(bb + 2) * Z_ + z], a2);
    atomicAdd(&g_z[(bb + 3) * Z_ + z], a3);
}

__global__ void __launch_bounds__(256) dec_lin(const float* __restrict__ Wd,
                                               const float* __restrict__ bd) {
    __shared__ float zsm[B_ * Z_];
    int t = threadIdx.x;
    for (int i = t; i < B_ * Z_; i += 256) zsm[i] = g_z[i];
    __syncthreads();
    constexpr int J4 = N1_ * C_ / 4;
    int j4 = blockIdx.x * 256 + t;
    if (j4 >= J4) return;
    const float4* W4 = (const float4*)Wd;
    float4 bias = __ldg(((const float4*)bd) + j4);
    float4 a[B_];
#pragma unroll
    for (int b = 0; b < B_; b++) a[b] = bias;
#pragma unroll 4
    for (int zk = 0; zk < Z_; zk++) {
        float4 w = __ldcs(W4 + (size_t)zk * J4 + j4);
#pragma unroll
        for (int b = 0; b < B_; b++) {
            float zv = zsm[b * Z_ + zk];
            a[b].x = fmaf(zv, w.x, a[b].x);
            a[b].y = fmaf(zv, w.y, a[b].y);
            a[b].z = fmaf(zv, w.z, a[b].z);
            a[b].w = fmaf(zv, w.w, a[b].w);
        }
    }
    float4* out4 = (float4*)g_hc2;
#pragma unroll
    for (int b = 0; b < B_; b++) {
        float4 r = a[b];
        r.x = fmaxf(r.x, 0.f); r.y = fmaxf(r.y, 0.f);
        r.z = fmaxf(r.z, 0.f); r.w = fmaxf(r.w, 0.f);
        out4[(size_t)b * J4 + j4] = r;
    }
}

// ---------------- pure-gather Cheb step (R14 proven: y=1 full vertex, 2-edge unroll) ---------
template <bool K1>
__global__ void __launch_bounds__(256) cheb_step(int prev_idx, int pp_idx, int next_idx) {
    int w = (blockIdx.x * blockDim.x + threadIdx.x) >> 5;
    if (w >= N0_) return;
    int lane = threadIdx.x & 31;

    const float4* Tp = g_buf[prev_idx];
    int beg = g_rowptr[w], end = g_rowptr[w + 1];
    float4 sA = make_float4(0.f, 0.f, 0.f, 0.f);
    float4 sB = make_float4(0.f, 0.f, 0.f, 0.f);
    for (int p = beg; p < end; p += 2) {
        int2 e0 = g_edges[p];
        int2 e1 = g_edges[p + 1];
        const float4* q0 = Tp + (size_t)e0.x * 64;
        const float4* q1 = Tp + (size_t)e1.x * 64;
        float4 a0 = q0[lane], b0 = q0[lane + 32];
        float4 a1 = q1[lane], b1 = q1[lane + 32];
        float n0 = __int_as_float(e0.y), n1 = __int_as_float(e1.y);
        sA.x = fmaf(n0, a0.x, sA.x); sA.y = fmaf(n0, a0.y, sA.y);
        sA.z = fmaf(n0, a0.z, sA.z); sA.w = fmaf(n0, a0.w, sA.w);
        sB.x = fmaf(n0, b0.x, sB.x); sB.y = fmaf(n0, b0.y, sB.y);
        sB.z = fmaf(n0, b0.z, sB.z); sB.w = fmaf(n0, b0.w, sB.w);
        sA.x = fmaf(n1, a1.x, sA.x); sA.y = fmaf(n1, a1.y, sA.y);
        sA.z = fmaf(n1, a1.z, sA.z); sA.w = fmaf(n1, a1.w, sA.w);
        sB.x = fmaf(n1, b1.x, sB.x); sB.y = fmaf(n1, b1.y, sB.y);
        sB.z = fmaf(n1, b1.z, sB.z); sB.w = fmaf(n1, b1.w, sB.w);
    }

    size_t base = (size_t)w * 64;
    float4 tA, tB;
    if (K1) {
        tA = sA; tB = sB;
    } else {
        const float4* Tpp = g_buf[pp_idx];
        float4 pA = Tpp[base + lane];
        float4 pB = Tpp[base + 32 + lane];
        tA = make_float4(2.f * sA.x - pA.x, 2.f * sA.y - pA.y,
                         2.f * sA.z - pA.z, 2.f * sA.w - pA.w);
        tB = make_float4(2.f * sB.x - pB.x, 2.f * sB.y - pB.y,
                         2.f * sB.z - pB.z, 2.f * sB.w - pB.w);
    }
    float4* Tn = g_buf[next_idx];
    Tn[base + lane]      = tA;
    Tn[base + 32 + lane] = tB;
}

// ---------------- fused final step + combine32 (conv0) ----------------
__global__ void __launch_bounds__(256) fused_step_combine32(
    int prev_idx, int pp_idx,
    int i0, int i1, int i2, int i3, int i4,
    const float* __restrict__ W, const float* __restrict__ bias, int relu_out_idx) {
    __shared__ __align__(16) float tkbuf[8][256];
    int w = (blockIdx.x * blockDim.x + threadIdx.x) >> 5;
    if (w >= N0_) return;
    int lane = threadIdx.x & 31;
    int warp = threadIdx.x >> 5;

    // gather (full vertex, 2-edge unroll, 2 x LDG.128 per edge)
    const float4* Tp = g_buf[prev_idx];
    int beg = g_rowptr[w], end = g_rowptr[w + 1];
    float4 sA = make_float4(0.f, 0.f, 0.f, 0.f);
    float4 sB = make_float4(0.f, 0.f, 0.f, 0.f);
    for (int p = beg; p < end; p += 2) {
        int2 e0 = g_edges[p];
        int2 e1 = g_edges[p + 1];
        const float4* q0 = Tp + (size_t)e0.x * 64;
        const float4* q1 = Tp + (size_t)e1.x * 64;
        float4 a0 = q0[lane], b0 = q0[lane + 32];
        float4 a1 = q1[lane], b1 = q1[lane + 32];
        float n0 = __int_as_float(e0.y), n1 = __int_as_float(e1.y);
        sA.x = fmaf(n0, a0.x, sA.x); sA.y = fmaf(n0, a0.y, sA.y);
        sA.z = fmaf(n0, a0.z, sA.z); sA.w = fmaf(n0, a0.w, sA.w);
        sB.x = fmaf(n0, b0.x, sB.x); sB.y = fmaf(n0, b0.y, sB.y);
        sB.z = fmaf(n0, b0.z, sB.z); sB.w = fmaf(n0, b0.w, sB.w);
        sA.x = fmaf(n1, a1.x, sA.x); sA.y = fmaf(n1, a1.y, sA.y);
        sA.z = fmaf(n1, a1.z, sA.z); sA.w = fmaf(n1, a1.w, sA.w);
        sB.x = fmaf(n1, b1.x, sB.x); sB.y = fmaf(n1, b1.y, sB.y);
        sB.z = fmaf(n1, b1.z, sB.z); sB.w = fmaf(n1, b1.w, sB.w);
    }
    size_t vb = (size_t)w * 64;
    float4 pA = g_buf[pp_idx][vb + lane];
    float4 pB = g_buf[pp_idx][vb + 32 + lane];
    float4 t5A = make_float4(2.f * sA.x - pA.x, 2.f * sA.y - pA.y,
                             2.f * sA.z - pA.z, 2.f * sA.w - pA.w);
    float4 t5B = make_float4(2.f * sB.x - pB.x, 2.f * sB.y - pB.y,
                             2.f * sB.z - pB.z, 2.f * sB.w - pB.w);

    // combine
    float acc[B_];
    float binit = bias[lane];
#pragma unroll
    for (int b = 0; b < B_; b++) acc[b] = binit;

    int idxs[5] = {i0, i1, i2, i3, i4};
    float4* tb4 = (float4*)&tkbuf[warp][0];
#pragma unroll
    for (int k = 0; k < 6; k++) {
        if (k < 5) {
            const float4* T4 = g_buf[idxs[k]];
            tb4[lane]      = T4[vb + lane];
            tb4[lane + 32] = T4[vb + 32 + lane];
        } else {
            tb4[lane]      = t5A;
            tb4[lane + 32] = t5B;
        }
        __syncwarp();
        const float* Wk = W + k * C_ * C_;
        u64 w2p[16];
#pragma unroll
        for (int i = 0; i < 16; i++)
            w2p[i] = pack2(Wk[(2 * i) * C_ + lane], Wk[(2 * i + 1) * C_ + lane]);
#pragma unroll
        for (int b = 0; b < B_; b++) {
            const u64* tb = (const u64*)&tkbuf[warp][b * 32];
            u64 a2 = 0;
#pragma unroll
            for (int i = 0; i < 16; i++) fma2(a2, tb[i], w2p[i]);
            float2 cc = unpack2(a2);
            acc[b] += cc.x + cc.y;
        }
        __syncwarp();
    }

    float* outp = (float*)g_buf[relu_out_idx];
#pragma unroll
    for (int b = 0; b < B_; b++)
        outp[vb * 4 + b * 32 + lane] = fmaxf(acc[b], 0.f);
}

// ---------------- fused final step + combine3 (conv1, no bias) ----------------
__global__ void __launch_bounds__(256) fused_step_combine3(
    int prev_idx, int pp_idx,
    int i0, int i1, int i2, int i3, int i4,
    const float* __restrict__ W, float* __restrict__ out3) {
    __shared__ __align__(16) float tkbuf[8][256];
    int gt = blockIdx.x * blockDim.x + threadIdx.x;
    if (gt < N0_) g_cnt[gt] = 0;                   // fold next-call reset into last kernel
    int w = gt >> 5;
    if (w >= N0_) return;
    int lane = threadIdx.x & 31;
    int warp = threadIdx.x >> 5;

    // gather
    const float4* Tp = g_buf[prev_idx];
    int beg = g_rowptr[w], end = g_rowptr[w + 1];
    float4 sA = make_float4(0.f, 0.f, 0.f, 0.f);
    float4 sB = make_float4(0.f, 0.f, 0.f, 0.f);
    for (int p = beg; p < end; p += 2) {
        int2 e0 = g_edges[p];
        int2 e1 = g_edges[p + 1];
        const float4* q0 = Tp + (size_t)e0.x * 64;
        const float4* q1 = Tp + (size_t)e1.x * 64;
        float4 a0 = q0[lane], b0 = q0[lane + 32];
        float4 a1 = q1[lane], b1 = q1[lane + 32];
        float n0 = __int_as_float(e0.y), n1 = __int_as_float(e1.y);
        sA.x = fmaf(n0, a0.x, sA.x); sA.y = fmaf(n0, a0.y, sA.y);
        sA.z = fmaf(n0, a0.z, sA.z); sA.w = fmaf(n0, a0.w, sA.w);
        sB.x = fmaf(n0, b0.x, sB.x); sB.y = fmaf(n0, b0.y, sB.y);
        sB.z = fmaf(n0, b0.z, sB.z); sB.w = fmaf(n0, b0.w, sB.w);
        sA.x = fmaf(n1, a1.x, sA.x); sA.y = fmaf(n1, a1.y, sA.y);
        sA.z = fmaf(n1, a1.z, sA.z); sA.w = fmaf(n1, a1.w, sA.w);
        sB.x = fmaf(n1, b1.x, sB.x); sB.y = fmaf(n1, b1.y, sB.y);
        sB.z = fmaf(n1, b1.z, sB.z); sB.w = fmaf(n1, b1.w, sB.w);
    }
    size_t vb = (size_t)w * 64;
    float4 pA = g_buf[pp_idx][vb + lane];
    float4 pB = g_buf[pp_idx][vb + 32 + lane];
    float4 t5A = make_float4(2.f * sA.x - pA.x, 2.f * sA.y - pA.y,
                             2.f * sA.z - pA.z, 2.f * sA.w - pA.w);
    float4 t5B = make_float4(2.f * sB.x - pB.x, 2.f * sB.y - pB.y,
                             2.f * sB.z - pB.z, 2.f * sB.w - pB.w);

    bool act = lane < 24;
    int b = act ? lane / 3 : 0;
    int c = act ? lane - 3 * (lane / 3) : 0;

    float acc = 0.f;
    int idxs[5] = {i0, i1, i2, i3, i4};
    float4* tb4 = (float4*)&tkbuf[warp][0];
#pragma unroll
    for (int k = 0; k < 6; k++) {
        if (k < 5) {
            const float4* T4 = g_buf[idxs[k]];
            tb4[lane]      = T4[vb + lane];
            tb4[lane + 32] = T4[vb + 32 + lane];
        } else {
            tb4[lane]      = t5A;
            tb4[lane + 32] = t5B;
        }
        __syncwarp();
        const float* Wk = W + k * C_ * FIN_;       // [32][3]
        const u64* tb = (const u64*)&tkbuf[warp][b * 32];
        u64 a2 = 0;
#pragma unroll
        for (int i = 0; i < 16; i++) {
            u64 wp = pack2(Wk[(2 * i) * FIN_ + c], Wk[(2 * i + 1) * FIN_ + c]);
            fma2(a2, tb[i], wp);
        }
        float2 cc = unpack2(a2);
        acc += cc.x + cc.y;
        __syncwarp();
    }

    if (act)
        out3[((size_t)b * N0_ + w) * FIN_ + c] = acc;
}

// ---------------- launch ----------------
extern "C" void kernel_launch(void* const* d_in, const int* in_sizes, int n_in,
                              void* d_out, int out_size) {
    (void)in_sizes; (void)n_in; (void)out_size;
    const float* x      = (const float*)d_in[0];
    const int*   eidx   = (const int*)  d_in[1];
    const float* Anorm  = (const float*)d_in[2];
    const int*   didx   = (const int*)  d_in[3];
    const float* dval   = (const float*)d_in[4];
    const int*   uidx   = (const int*)  d_in[5];
    const float* uval   = (const float*)d_in[6];
    const float* Wenc0  = (const float*)d_in[7];
    const float* benc0  = (const float*)d_in[8];
    const float* Wdec0  = (const float*)d_in[9];
    const float* bdec0  = (const float*)d_in[10];
    const float* Wdec1  = (const float*)d_in[11];
    const float* encW   = (const float*)d_in[12];
    const float* encb   = (const float*)d_in[13];
    const float* decW   = (const float*)d_in[14];
    const float* decb   = (const float*)d_in[15];
    float* out = (float*)d_out;

    const int GPV  = N0_ * 32 / 256;          // 6250 warp-per-vertex
    const int GE   = (E_ + 255) / 256;
    const int GN0  = (N0_ + 255) / 256;
    const int GPREP = (XT_N_ + 255) / 256;

    // CSR prep
    k_prep<<<GPREP, 256>>>(eidx + E_, x, encb);
    k_scan<<<1, 1024>>>();
    k_fill<<<GE, 256>>>(eidx, eidx + E_, Anorm);
    k_pad<<<GN0, 256>>>();

    // ---- encoder conv ----
    enc_prop<<<GPV, 256>>>(-1, -2, 0);   // T1
    enc_prop<<<GPV, 256>>>( 0, -1, 1);   // T2
    enc_prop<<<GPV, 256>>>( 1,  0, 2);   // T3
    enc_prop<<<GPV, 256>>>( 2,  1, 3);   // T4
    enc_prop<<<GPV, 256>>>( 3,  2, 4);   // T5
    enc_combine<<<GPV, 256>>>(Wenc0, benc0);

    // ---- down pool ----
    down_pool<<<B_ * N1_ * 32 / 256, 256>>>(didx + DOWN_NNZ_, dval);

    // ---- encoder linear ----
    enc_lin<<<(N1_ * C_ + 511) / 512, 256>>>(encW);

    // ---- decoder linear (+relu) ----
    dec_lin<<<(N1_ * C_ / 4 + 255) / 256, 256>>>(decW, decb);

    // ---- up pool -> g_buf[0] vertex-major ----
    up_pool<<<B_ * N0_ * 32 / 256, 256>>>(uidx + UP_NNZ_, uval);

    // ---- decoder conv0: T1..T4 -> g_buf[1..4]; fused T5+combine -> relu -> g_buf[6] ----
    cheb_step<true ><<<GPV, 256>>>(0, 0, 1);
    cheb_step<false><<<GPV, 256>>>(1, 0, 2);
    cheb_step<false><<<GPV, 256>>>(2, 1, 3);
    cheb_step<false><<<GPV, 256>>>(3, 2, 4);
    fused_step_combine32<<<GPV, 256>>>(4, 3, 0, 1, 2, 3, 4, Wdec0, bdec0, 6);

    // ---- decoder conv1: T0 = g_buf[6]; T1..T4 -> g_buf[0..3]; fused T5+combine -> d_out ----
    cheb_step<true ><<<GPV, 256>>>(6, 0, 0);
    cheb_step<false><<<GPV, 256>>>(0, 6, 1);
    cheb_step<false><<<GPV, 256>>>(1, 0, 2);
    cheb_step<false><<<GPV, 256>>>(2, 1, 3);
    fused_step_combine3<<<GPV, 256>>>(3, 2, 6, 0, 1, 2, 3, Wdec1, out);
}